// round 15
// baseline (speedup 1.0000x reference)
#include <cuda_runtime.h>
#include <cuda_bf16.h>
#include <math.h>

// ---------------------------------------------------------------------------
// FraudGNN: 3-layer GCN, N=50000 nodes, E=800000 edges (int32 edge_index).
// R15 (bisect of R14 regression): layer-1 TC GEMM keeps double-buffered W
// staging (measured 43us); layer-2 TC GEMM reverted to R13 single-buffer
// CK=8 (was measured-fast at 4 blocks/SM). Dual stats buffers retained.
// ---------------------------------------------------------------------------

#define NMAX 50000
#define EMAX 800000

__device__ float g_bufA[NMAX * 128];
__device__ float g_bufB[NMAX * 128];
__device__ float g_dinv[NMAX];
__device__ float g_stats[512];        // [0..255] layer1, [256..511] layer2
__device__ int   g_counts[NMAX];
__device__ int   g_offsets[NMAX + 1];
__device__ int   g_cursor[NMAX];
__device__ int   g_csr_src[EMAX];

// ---------------------------------------------------------------------------
__device__ __forceinline__ unsigned f2tf32(float f) {
    unsigned u;
    asm("cvt.rna.tf32.f32 %0, %1;" : "=r"(u) : "f"(f));
    return u;
}

__device__ __forceinline__ void mma_tf32(float* c, const unsigned* a,
                                         unsigned b0, unsigned b1) {
    asm volatile(
        "mma.sync.aligned.m16n8k8.row.col.f32.tf32.tf32.f32 "
        "{%0,%1,%2,%3},{%4,%5,%6,%7},{%8,%9},{%0,%1,%2,%3};"
        : "+f"(c[0]), "+f"(c[1]), "+f"(c[2]), "+f"(c[3])
        : "r"(a[0]), "r"(a[1]), "r"(a[2]), "r"(a[3]), "r"(b0), "r"(b1));
}

__device__ __forceinline__ void split_store_w4(float* dhi, float* dlo,
                                               int kk, int mm, int MP,
                                               float4 w) {
    float4 h, l;
    h.x = __uint_as_float(f2tf32(w.x)); l.x = __uint_as_float(f2tf32(w.x - h.x));
    h.y = __uint_as_float(f2tf32(w.y)); l.y = __uint_as_float(f2tf32(w.y - h.y));
    h.z = __uint_as_float(f2tf32(w.z)); l.z = __uint_as_float(f2tf32(w.z - h.z));
    h.w = __uint_as_float(f2tf32(w.w)); l.w = __uint_as_float(f2tf32(w.w - h.w));
    *(float4*)&dhi[kk * MP + mm * 4] = h;
    *(float4*)&dlo[kk * MP + mm * 4] = l;
}

// ---------------------------------------------------------------------------
__global__ void hist_kernel(const int* __restrict__ ei, long long E,
                            int* __restrict__ counts) {
    long long e = blockIdx.x * (long long)blockDim.x + threadIdx.x;
    if (e < E) atomicAdd(&counts[ei[E + e]], 1);
}

__global__ void scan_kernel(const int* __restrict__ counts,
                            int* __restrict__ offsets,
                            float* __restrict__ dinv, int n) {
    __shared__ int partial[1024];
    const int t = threadIdx.x;
    const int chunk = (n + 1023) / 1024;
    const int begin = t * chunk;
    const int end = min(begin + chunk, n);
    int s = 0;
#pragma unroll 4
    for (int i = begin; i < end; i++) s += counts[i];
    partial[t] = s;
    __syncthreads();
    for (int off = 1; off < 1024; off <<= 1) {
        int x = (t >= off) ? partial[t - off] : 0;
        __syncthreads();
        partial[t] += x;
        __syncthreads();
    }
    int running = partial[t] - s;
    for (int i = begin; i < end; i++) {
        offsets[i] = running;
        int c = counts[i];
        running += c;
        dinv[i] = rsqrtf((float)c + 1.0f);
    }
    if (t == 1023) offsets[n] = partial[1023];
}

__global__ void scatter_kernel(const int* __restrict__ ei, long long E,
                               int* __restrict__ cursor,
                               int* __restrict__ csr_src) {
    long long e = blockIdx.x * (long long)blockDim.x + threadIdx.x;
    if (e < E) {
        int s = ei[e];
        int d = ei[E + e];
        int pos = atomicAdd(&cursor[d], 1);
        csr_src[pos] = s;
    }
}

// ---------------------------------------------------------------------------
// Tensor-core GEMM: out[n,M] = act(X)[n,K] @ W[K,M] (optionally * dinv),
// m16n8k8 tf32 / 3xTF32. ROWS=64/block; warp (wq,wh) owns 16 rows x M/2.
// PIPE=true: W double-buffered with register prefetch (1 sync/chunk).
// PIPE=false: single W buffer, 2 syncs/chunk (R13 behavior).
// W row stride MP=M+8 -> conflict-free B-frag LDS.
template <int K, int M, bool BN, bool SCALE, int MAXB, int CK, bool PIPE>
__global__ void __launch_bounds__(256, MAXB)
gemm_tc_kernel(const float* __restrict__ X,
               const float* __restrict__ W,
               float* __restrict__ out, int n,
               const float* __restrict__ stats,
               const float* __restrict__ g,
               const float* __restrict__ beta,
               const float* __restrict__ dinv) {
    constexpr int ROWS = 64;
    constexpr int KP   = K + 4;
    constexpr int MP   = M + 8;
    constexpr int NT   = M / 16;
    constexpr int NC   = K / CK;
    constexpr int M4   = M / 4;
    constexpr int NBUF = PIPE ? 2 : 1;
    constexpr int PF   = (CK * M4 + 255) / 256;

    extern __shared__ float sh[];
    float* xs     = sh;                           // ROWS*KP
    float* wbuf   = xs + ROWS * KP;               // NBUF*2*CK*MP
    float* sscale = wbuf + NBUF * 2 * CK * MP;    // K
    float* sshift = sscale + K;                   // K

    const int tid  = threadIdx.x;
    const int lane = tid & 31;
    const int wid  = tid >> 5;

    if (BN) {
        for (int f = tid; f < K; f += 256) {
            float inv_n = 1.0f / (float)n;
            float m = stats[f] * inv_n;
            float v = stats[128 + f] * inv_n - m * m;
            float sc = g[f] * rsqrtf(v + 1e-5f);
            sscale[f] = sc;
            sshift[f] = beta[f] - m * sc;
        }
        __syncthreads();
    }

    const int base = blockIdx.x * ROWS;
    constexpr int K4 = K / 4;
    for (int i = tid; i < ROWS * K4; i += 256) {
        int rr = i / K4, kk = i % K4;
        int row = base + rr;
        float4 v = make_float4(0.f, 0.f, 0.f, 0.f);
        if (row < n) {
            v = *(const float4*)(X + (long long)row * K + kk * 4);
            if (BN) {
                int f = kk * 4;
                v.x = fmaxf(fmaf(v.x, sscale[f + 0], sshift[f + 0]), 0.f);
                v.y = fmaxf(fmaf(v.y, sscale[f + 1], sshift[f + 1]), 0.f);
                v.z = fmaxf(fmaf(v.z, sscale[f + 2], sshift[f + 2]), 0.f);
                v.w = fmaxf(fmaf(v.w, sscale[f + 3], sshift[f + 3]), 0.f);
            }
        }
        *(float4*)&xs[rr * KP + kk * 4] = v;
    }

    const int fr = lane >> 2;
    const int fc = lane & 3;
    const int wq = wid & 3;
    const int wh = wid >> 2;
    const int wrow = wq * 16;
    const int ncol0 = wh * (M / 2);

    float acc[NT][4];
#pragma unroll
    for (int t = 0; t < NT; t++)
#pragma unroll
        for (int j = 0; j < 4; j++) acc[t][j] = 0.0f;

    const float* xw0 = xs + (wrow + fr) * KP;
    const float* xw1 = xs + (wrow + fr + 8) * KP;

    if (PIPE) {
        // prologue: prefetch chunk 0, split into buffer 0
        float4 pf[PF];
#pragma unroll
        for (int p = 0; p < PF; p++) {
            int i = tid + p * 256;
            if (i < CK * M4)
                pf[p] = __ldg((const float4*)(W + (i / M4) * M + (i % M4) * 4));
        }
#pragma unroll
        for (int p = 0; p < PF; p++) {
            int i = tid + p * 256;
            if (i < CK * M4)
                split_store_w4(wbuf, wbuf + CK * MP, i / M4, i % M4, MP, pf[p]);
        }
        __syncthreads();

        for (int ck = 0; ck < NC; ck++) {
            const int cur = ck & 1;
            if (ck + 1 < NC) {
#pragma unroll
                for (int p = 0; p < PF; p++) {
                    int i = tid + p * 256;
                    if (i < CK * M4)
                        pf[p] = __ldg((const float4*)(
                            W + ((ck + 1) * CK + i / M4) * M + (i % M4) * 4));
                }
            }
            const float* whi = wbuf + cur * 2 * CK * MP;
            const float* wlo = whi + CK * MP;
#pragma unroll
            for (int kc = 0; kc < CK / 8; kc++) {
                const int kg = ck * CK + kc * 8 + fc;
                float af0 = xw0[kg], af1 = xw1[kg];
                float af2 = xw0[kg + 4], af3 = xw1[kg + 4];
                unsigned ah[4], al[4];
                ah[0] = f2tf32(af0); al[0] = f2tf32(af0 - __uint_as_float(ah[0]));
                ah[1] = f2tf32(af1); al[1] = f2tf32(af1 - __uint_as_float(ah[1]));
                ah[2] = f2tf32(af2); al[2] = f2tf32(af2 - __uint_as_float(ah[2]));
                ah[3] = f2tf32(af3); al[3] = f2tf32(af3 - __uint_as_float(ah[3]));
                const int kl0 = (kc * 8 + fc) * MP;
                const int kl1 = kl0 + 4 * MP;
#pragma unroll
                for (int t = 0; t < NT; t++) {
                    const int cb = ncol0 + t * 8 + fr;
                    unsigned bh0 = __float_as_uint(whi[kl0 + cb]);
                    unsigned bh1 = __float_as_uint(whi[kl1 + cb]);
                    unsigned bl0 = __float_as_uint(wlo[kl0 + cb]);
                    unsigned bl1 = __float_as_uint(wlo[kl1 + cb]);
                    mma_tf32(acc[t], ah, bh0, bh1);
                    mma_tf32(acc[t], al, bh0, bh1);
                    mma_tf32(acc[t], ah, bl0, bl1);
                }
            }
            if (ck + 1 < NC) {
                float* dhi = wbuf + (1 - cur) * 2 * CK * MP;
                float* dlo = dhi + CK * MP;
#pragma unroll
                for (int p = 0; p < PF; p++) {
                    int i = tid + p * 256;
                    if (i < CK * M4)
                        split_store_w4(dhi, dlo, i / M4, i % M4, MP, pf[p]);
                }
                __syncthreads();
            }
        }
    } else {
        // single-buffer path (R13): stage chunk, sync, MMA, sync
        for (int ck = 0; ck < NC; ck++) {
            __syncthreads();
            float* dhi = wbuf;
            float* dlo = wbuf + CK * MP;
            for (int i = tid; i < CK * M4; i += 256) {
                float4 w = __ldg((const float4*)(
                    W + (ck * CK + i / M4) * M + (i % M4) * 4));
                split_store_w4(dhi, dlo, i / M4, i % M4, MP, w);
            }
            __syncthreads();
#pragma unroll
            for (int kc = 0; kc < CK / 8; kc++) {
                const int kg = ck * CK + kc * 8 + fc;
                float af0 = xw0[kg], af1 = xw1[kg];
                float af2 = xw0[kg + 4], af3 = xw1[kg + 4];
                unsigned ah[4], al[4];
                ah[0] = f2tf32(af0); al[0] = f2tf32(af0 - __uint_as_float(ah[0]));
                ah[1] = f2tf32(af1); al[1] = f2tf32(af1 - __uint_as_float(ah[1]));
                ah[2] = f2tf32(af2); al[2] = f2tf32(af2 - __uint_as_float(ah[2]));
                ah[3] = f2tf32(af3); al[3] = f2tf32(af3 - __uint_as_float(ah[3]));
                const int kl0 = (kc * 8 + fc) * MP;
                const int kl1 = kl0 + 4 * MP;
#pragma unroll
                for (int t = 0; t < NT; t++) {
                    const int cb = ncol0 + t * 8 + fr;
                    unsigned bh0 = __float_as_uint(dhi[kl0 + cb]);
                    unsigned bh1 = __float_as_uint(dhi[kl1 + cb]);
                    unsigned bl0 = __float_as_uint(dlo[kl0 + cb]);
                    unsigned bl1 = __float_as_uint(dlo[kl1 + cb]);
                    mma_tf32(acc[t], ah, bh0, bh1);
                    mma_tf32(acc[t], al, bh0, bh1);
                    mma_tf32(acc[t], ah, bl0, bl1);
                }
            }
        }
    }

    // epilogue
    const int row0 = base + wrow + fr;
    const int row1 = row0 + 8;
    float s0 = 1.0f, s1 = 1.0f;
    if (SCALE) {
        if (row0 < n) s0 = dinv[row0];
        if (row1 < n) s1 = dinv[row1];
    }
#pragma unroll
    for (int t = 0; t < NT; t++) {
        const int col = ncol0 + t * 8 + 2 * fc;
        if (row0 < n)
            *(float2*)&out[(long long)row0 * M + col] =
                make_float2(acc[t][0] * s0, acc[t][1] * s0);
        if (row1 < n)
            *(float2*)&out[(long long)row1 * M + col] =
                make_float2(acc[t][2] * s1, acc[t][3] * s1);
    }
}

// Small GEMM for M=2 (layer 3), BN+ReLU fused on load, output scaled by dinv.
template <int K>
__global__ void gemm2_bn_kernel(const float* __restrict__ X,
                                const float* __restrict__ W,
                                float* __restrict__ out, int n,
                                const float* __restrict__ stats,
                                const float* __restrict__ g,
                                const float* __restrict__ beta,
                                const float* __restrict__ dinv) {
    __shared__ float Ws[K * 2];
    __shared__ float sscale[K];
    __shared__ float sshift[K];
    __shared__ float xs[128 * K];
    const int tid = threadIdx.x;

    if (tid < K) {
        float inv_n = 1.0f / (float)n;
        float m = stats[tid] * inv_n;
        float v = stats[128 + tid] * inv_n - m * m;
        float sc = g[tid] * rsqrtf(v + 1e-5f);
        sscale[tid] = sc;
        sshift[tid] = beta[tid] - m * sc;
    }
    for (int i = tid; i < K * 2; i += 256) Ws[i] = W[i];
    __syncthreads();

    const int base = blockIdx.x * 128;
    constexpr int K4 = K / 4;
    for (int i = tid; i < 128 * K4; i += 256) {
        int rr = i / K4, kk = i % K4;
        int row = base + rr;
        float4 v = make_float4(0.f, 0.f, 0.f, 0.f);
        if (row < n) {
            v = *(const float4*)(X + (long long)row * K + kk * 4);
            int f = kk * 4;
            v.x = fmaxf(fmaf(v.x, sscale[f + 0], sshift[f + 0]), 0.f);
            v.y = fmaxf(fmaf(v.y, sscale[f + 1], sshift[f + 1]), 0.f);
            v.z = fmaxf(fmaf(v.z, sscale[f + 2], sshift[f + 2]), 0.f);
            v.w = fmaxf(fmaf(v.w, sscale[f + 3], sshift[f + 3]), 0.f);
        }
        *(float4*)&xs[rr * K + kk * 4] = v;
    }
    __syncthreads();

    const int col = tid % 2;
    const int r   = tid / 2;
    int row = base + r;
    if (row < n) {
        float acc = 0.0f;
        const float* xrow = xs + r * K;
#pragma unroll
        for (int k = 0; k < K; k++) acc = fmaf(xrow[k], Ws[k * 2 + col], acc);
        out[(long long)row * 2 + col] = acc * dinv[row];
    }
}

// ---------------------------------------------------------------------------
// CSR pull-aggregation, F=128, UNSCALED input h (layer 1).
__global__ void __launch_bounds__(256)
csr_agg128_kernel(const int* __restrict__ csr_src,
                  const int* __restrict__ offsets,
                  const float* __restrict__ h,
                  const float* __restrict__ dinv,
                  const float* __restrict__ b,
                  float* __restrict__ out, int n,
                  float* __restrict__ stats) {
    __shared__ float ssum[128];
    __shared__ float ssq[128];
    const int tid  = threadIdx.x;
    const int lane = tid & 31;
    const int wid  = tid >> 5;
    if (tid < 128) { ssum[tid] = 0.f; ssq[tid] = 0.f; }
    __syncthreads();

    const float4* h4 = (const float4*)h;
    float4* out4 = (float4*)out;
    float4 bv = ((const float4*)b)[lane];

    float4 lsum = make_float4(0.f, 0.f, 0.f, 0.f);
    float4 lsq  = make_float4(0.f, 0.f, 0.f, 0.f);

    for (int node = blockIdx.x * 8 + wid; node < n; node += gridDim.x * 8) {
        const int e0 = offsets[node];
        const int e1 = offsets[node + 1];
        const float dn = dinv[node];
        float4 acc = make_float4(0.f, 0.f, 0.f, 0.f);

        int j = e0;
        for (; j + 4 <= e1; j += 4) {
            int sa = csr_src[j],     sb = csr_src[j + 1];
            int sc = csr_src[j + 2], sd = csr_src[j + 3];
            float na = dinv[sa] * dn, nb = dinv[sb] * dn;
            float nc = dinv[sc] * dn, nd = dinv[sd] * dn;
            float4 va = h4[(long long)sa * 32 + lane];
            float4 vb = h4[(long long)sb * 32 + lane];
            float4 vc = h4[(long long)sc * 32 + lane];
            float4 vd = h4[(long long)sd * 32 + lane];
            acc.x += va.x * na + vb.x * nb + vc.x * nc + vd.x * nd;
            acc.y += va.y * na + vb.y * nb + vc.y * nc + vd.y * nd;
            acc.z += va.z * na + vb.z * nb + vc.z * nc + vd.z * nd;
            acc.w += va.w * na + vb.w * nb + vc.w * nc + vd.w * nd;
        }
        for (; j < e1; j++) {
            int s = csr_src[j];
            float nm = dinv[s] * dn;
            float4 v = h4[(long long)s * 32 + lane];
            acc.x += v.x * nm; acc.y += v.y * nm;
            acc.z += v.z * nm; acc.w += v.w * nm;
        }
        float4 hv = h4[(long long)node * 32 + lane];
        float d2 = dn * dn;
        acc.x = fmaf(hv.x, d2, acc.x) + bv.x;
        acc.y = fmaf(hv.y, d2, acc.y) + bv.y;
        acc.z = fmaf(hv.z, d2, acc.z) + bv.z;
        acc.w = fmaf(hv.w, d2, acc.w) + bv.w;
        out4[(long long)node * 32 + lane] = acc;

        lsum.x += acc.x; lsum.y += acc.y; lsum.z += acc.z; lsum.w += acc.w;
        lsq.x = fmaf(acc.x, acc.x, lsq.x); lsq.y = fmaf(acc.y, acc.y, lsq.y);
        lsq.z = fmaf(acc.z, acc.z, lsq.z); lsq.w = fmaf(acc.w, acc.w, lsq.w);
    }

    atomicAdd(&ssum[lane * 4 + 0], lsum.x);
    atomicAdd(&ssum[lane * 4 + 1], lsum.y);
    atomicAdd(&ssum[lane * 4 + 2], lsum.z);
    atomicAdd(&ssum[lane * 4 + 3], lsum.w);
    atomicAdd(&ssq[lane * 4 + 0], lsq.x);
    atomicAdd(&ssq[lane * 4 + 1], lsq.y);
    atomicAdd(&ssq[lane * 4 + 2], lsq.z);
    atomicAdd(&ssq[lane * 4 + 3], lsq.w);
    __syncthreads();
    if (tid < 128) {
        atomicAdd(&stats[tid], ssum[tid]);
        atomicAdd(&stats[128 + tid], ssq[tid]);
    }
}

// F=64, PRE-SCALED input h' = h*dinv[src]; inner loop = pure adds.
__global__ void __launch_bounds__(256)
csr_agg64_kernel(const int* __restrict__ csr_src,
                 const int* __restrict__ offsets,
                 const float* __restrict__ h,
                 const float* __restrict__ dinv,
                 const float* __restrict__ b,
                 float* __restrict__ out, int n,
                 float* __restrict__ stats) {
    __shared__ float ssum[64];
    __shared__ float ssq[64];
    const int tid  = threadIdx.x;
    const int lane = tid & 31;
    const int wid  = tid >> 5;
    if (tid < 64) { ssum[tid] = 0.f; ssq[tid] = 0.f; }
    __syncthreads();

    const float2* h2 = (const float2*)h;
    float2* out2 = (float2*)out;
    float2 bv = ((const float2*)b)[lane];

    float2 lsum = make_float2(0.f, 0.f);
    float2 lsq  = make_float2(0.f, 0.f);

    for (int node = blockIdx.x * 8 + wid; node < n; node += gridDim.x * 8) {
        const int e0 = offsets[node];
        const int e1 = offsets[node + 1];
        const float dn = dinv[node];
        float2 acc = make_float2(0.f, 0.f);

        int j = e0;
        for (; j + 4 <= e1; j += 4) {
            int sa = csr_src[j],     sb = csr_src[j + 1];
            int sc = csr_src[j + 2], sd = csr_src[j + 3];
            float2 va = h2[(long long)sa * 32 + lane];
            float2 vb = h2[(long long)sb * 32 + lane];
            float2 vc = h2[(long long)sc * 32 + lane];
            float2 vd = h2[(long long)sd * 32 + lane];
            acc.x += va.x + vb.x + vc.x + vd.x;
            acc.y += va.y + vb.y + vc.y + vd.y;
        }
        for (; j < e1; j++) {
            int s = csr_src[j];
            float2 v = h2[(long long)s * 32 + lane];
            acc.x += v.x; acc.y += v.y;
        }
        float2 hv = h2[(long long)node * 32 + lane];
        float2 o;
        o.x = fmaf(dn, acc.x + hv.x, bv.x);
        o.y = fmaf(dn, acc.y + hv.y, bv.y);
        out2[(long long)node * 32 + lane] = o;

        lsum.x += o.x; lsum.y += o.y;
        lsq.x = fmaf(o.x, o.x, lsq.x);
        lsq.y = fmaf(o.y, o.y, lsq.y);
    }

    atomicAdd(&ssum[lane * 2 + 0], lsum.x);
    atomicAdd(&ssum[lane * 2 + 1], lsum.y);
    atomicAdd(&ssq[lane * 2 + 0], lsq.x);
    atomicAdd(&ssq[lane * 2 + 1], lsq.y);
    __syncthreads();
    if (tid < 64) {
        atomicAdd(&stats[tid], ssum[tid]);
        atomicAdd(&stats[128 + tid], ssq[tid]);
    }
}

// F=2, PRE-SCALED h'; fuses bias + log_softmax, writes d_out.
__global__ void __launch_bounds__(256)
csr_agg2_lsm_kernel(const int* __restrict__ csr_src,
                    const int* __restrict__ offsets,
                    const float* __restrict__ h,
                    const float* __restrict__ dinv,
                    const float* __restrict__ b,
                    float* __restrict__ out, int n) {
    int node = blockIdx.x * blockDim.x + threadIdx.x;
    if (node >= n) return;
    const float2* h2 = (const float2*)h;
    const int e0 = offsets[node];
    const int e1 = offsets[node + 1];
    const float dn = dinv[node];
    float ax = 0.f, ay = 0.f;
    int j = e0;
    for (; j + 4 <= e1; j += 4) {
        int sa = csr_src[j],     sb = csr_src[j + 1];
        int sc = csr_src[j + 2], sd = csr_src[j + 3];
        float2 va = h2[sa], vb = h2[sb], vc = h2[sc], vd = h2[sd];
        ax += va.x + vb.x + vc.x + vd.x;
        ay += va.y + vb.y + vc.y + vd.y;
    }
    for (; j < e1; j++) {
        float2 v = h2[csr_src[j]];
        ax += v.x; ay += v.y;
    }
    float2 hv = h2[node];
    float a = fmaf(dn, ax + hv.x, b[0]);
    float c = fmaf(dn, ay + hv.y, b[1]);
    float m = fmaxf(a, c);
    float l = m + logf(expf(a - m) + expf(c - m));
    out[2 * node]     = a - l;
    out[2 * node + 1] = c - l;
}

// ---------------------------------------------------------------------------
static inline int blocks_for(long long total, int tpb) {
    return (int)((total + tpb - 1) / tpb);
}

template <int K, int M, bool BN, bool SCALE, int MAXB, int CK, bool PIPE>
static void launch_gemm_tc(const float* X, const float* W, float* out, int n,
                           const float* stats, const float* g,
                           const float* beta, const float* dinv) {
    constexpr int ROWS = 64;
    constexpr int KP = K + 4;
    constexpr int MP = M + 8;
    constexpr int NBUF = PIPE ? 2 : 1;
    size_t sh = (size_t)(ROWS * KP + NBUF * 2 * CK * MP + 2 * K) * sizeof(float);
    cudaFuncSetAttribute(gemm_tc_kernel<K, M, BN, SCALE, MAXB, CK, PIPE>,
                         cudaFuncAttributeMaxDynamicSharedMemorySize, (int)sh);
    int grid = (n + ROWS - 1) / ROWS;
    gemm_tc_kernel<K, M, BN, SCALE, MAXB, CK, PIPE><<<grid, 256, sh>>>(
        X, W, out, n, stats, g, beta, dinv);
}

extern "C" void kernel_launch(void* const* d_in, const int* in_sizes, int n_in,
                              void* d_out, int out_size) {
    const float* x   = (const float*)d_in[0];
    const int*   ei  = (const int*)d_in[1];
    const float* W1 = (const float*)d_in[2];
    const float* b1 = (const float*)d_in[3];
    const float* g1 = (const float*)d_in[4];
    const float* be1= (const float*)d_in[5];
    const float* W2 = (const float*)d_in[6];
    const float* b2 = (const float*)d_in[7];
    const float* g2 = (const float*)d_in[8];
    const float* be2= (const float*)d_in[9];
    const float* W3 = (const float*)d_in[10];
    const float* b3 = (const float*)d_in[11];
    float* out = (float*)d_out;

    int       n = in_sizes[0] / 128;
    long long E = in_sizes[1] / 2;

    float *bufA, *bufB, *dinv, *stats;
    int *counts, *offsets, *cursor, *csr_src;
    cudaGetSymbolAddress((void**)&bufA,    g_bufA);
    cudaGetSymbolAddress((void**)&bufB,    g_bufB);
    cudaGetSymbolAddress((void**)&dinv,    g_dinv);
    cudaGetSymbolAddress((void**)&stats,   g_stats);
    cudaGetSymbolAddress((void**)&counts,  g_counts);
    cudaGetSymbolAddress((void**)&offsets, g_offsets);
    cudaGetSymbolAddress((void**)&cursor,  g_cursor);
    cudaGetSymbolAddress((void**)&csr_src, g_csr_src);
    float* statsA = stats;        // layer-1 BN stats
    float* statsB = stats + 256;  // layer-2 BN stats

    static cudaStream_t s_side = nullptr;
    static cudaEvent_t ev_fork = nullptr, ev_join = nullptr;
    if (s_side == nullptr) {
        cudaStreamCreateWithFlags(&s_side, cudaStreamNonBlocking);
        cudaEventCreateWithFlags(&ev_fork, cudaEventDisableTiming);
        cudaEventCreateWithFlags(&ev_join, cudaEventDisableTiming);
    }

    const int AGG_GRID = 1184;

    // ---- fork: CSR build + dinv + both stats zeroed on side stream ----------
    cudaEventRecord(ev_fork, 0);
    cudaStreamWaitEvent(s_side, ev_fork, 0);
    cudaMemsetAsync(counts, 0, (size_t)n * sizeof(int), s_side);
    hist_kernel<<<blocks_for(E, 256), 256, 0, s_side>>>(ei, E, counts);
    scan_kernel<<<1, 1024, 0, s_side>>>(counts, offsets, dinv, n);
    cudaMemcpyAsync(cursor, offsets, (size_t)n * sizeof(int),
                    cudaMemcpyDeviceToDevice, s_side);
    scatter_kernel<<<blocks_for(E, 256), 256, 0, s_side>>>(ei, E, cursor, csr_src);
    cudaMemsetAsync(stats, 0, 512 * sizeof(float), s_side);
    cudaEventRecord(ev_join, s_side);

    // ---- layer 1 TC-GEMM (pipelined; concurrent with CSR build) -------------
    launch_gemm_tc<128, 128, false, false, 3, 16, true>(
        x, W1, bufA, n, nullptr, nullptr, nullptr, nullptr);

    // ---- join, aggregation + rest of chain ----------------------------------
    cudaStreamWaitEvent(0, ev_join, 0);
    csr_agg128_kernel<<<AGG_GRID, 256>>>(csr_src, offsets, bufA, dinv, b1,
                                         bufB, n, statsA);

    // ---- layer 2: BN1+ReLU fused TC-GEMM(128->64) * dinv (R13 config) -------
    launch_gemm_tc<128, 64, true, true, 4, 8, false>(
        bufB, W2, bufA, n, statsA, g1, be1, dinv);
    csr_agg64_kernel<<<AGG_GRID, 256>>>(csr_src, offsets, bufA, dinv, b2,
                                        bufB, n, statsB);

    // ---- layer 3: BN2+ReLU fused GEMM(64->2) * dinv + agg + log_softmax -----
    gemm2_bn_kernel<64><<<blocks_for(n, 128), 256>>>(bufB, W3, bufA, n,
                                                     statsB, g2, be2, dinv);
    csr_agg2_lsm_kernel<<<blocks_for(n, 256), 256>>>(csr_src, offsets, bufA,
                                                     dinv, b3, out, n);
}

// round 16
// speedup vs baseline: 1.1898x; 1.1898x over previous
#include <cuda_runtime.h>
#include <cuda_bf16.h>
#include <math.h>

// ---------------------------------------------------------------------------
// FraudGNN: 3-layer GCN, N=50000 nodes, E=800000 edges (int32 edge_index).
// R16 = R13 config re-established (single-buffer W staging both TC GEMMs,
// CK=16 / CK=8, ROWS=64 tiling, MP=M+8 conflict-free, dinv folded into
// layer-2/3 epilogues) + dual stats buffers (no mid-chain memset).
// Purpose: controlled re-measurement after R14/R15 regressions that did not
// track per-kernel profile times (suspected machine variance vs pipelining
// interaction with the overlapped CSR build).
// ---------------------------------------------------------------------------

#define NMAX 50000
#define EMAX 800000

__device__ float g_bufA[NMAX * 128];
__device__ float g_bufB[NMAX * 128];
__device__ float g_dinv[NMAX];
__device__ float g_stats[512];        // [0..255] layer1, [256..511] layer2
__device__ int   g_counts[NMAX];
__device__ int   g_offsets[NMAX + 1];
__device__ int   g_cursor[NMAX];
__device__ int   g_csr_src[EMAX];

// ---------------------------------------------------------------------------
__device__ __forceinline__ unsigned f2tf32(float f) {
    unsigned u;
    asm("cvt.rna.tf32.f32 %0, %1;" : "=r"(u) : "f"(f));
    return u;
}

__device__ __forceinline__ void mma_tf32(float* c, const unsigned* a,
                                         unsigned b0, unsigned b1) {
    asm volatile(
        "mma.sync.aligned.m16n8k8.row.col.f32.tf32.tf32.f32 "
        "{%0,%1,%2,%3},{%4,%5,%6,%7},{%8,%9},{%0,%1,%2,%3};"
        : "+f"(c[0]), "+f"(c[1]), "+f"(c[2]), "+f"(c[3])
        : "r"(a[0]), "r"(a[1]), "r"(a[2]), "r"(a[3]), "r"(b0), "r"(b1));
}

// ---------------------------------------------------------------------------
__global__ void hist_kernel(const int* __restrict__ ei, long long E,
                            int* __restrict__ counts) {
    long long e = blockIdx.x * (long long)blockDim.x + threadIdx.x;
    if (e < E) atomicAdd(&counts[ei[E + e]], 1);
}

__global__ void scan_kernel(const int* __restrict__ counts,
                            int* __restrict__ offsets,
                            float* __restrict__ dinv, int n) {
    __shared__ int partial[1024];
    const int t = threadIdx.x;
    const int chunk = (n + 1023) / 1024;
    const int begin = t * chunk;
    const int end = min(begin + chunk, n);
    int s = 0;
#pragma unroll 4
    for (int i = begin; i < end; i++) s += counts[i];
    partial[t] = s;
    __syncthreads();
    for (int off = 1; off < 1024; off <<= 1) {
        int x = (t >= off) ? partial[t - off] : 0;
        __syncthreads();
        partial[t] += x;
        __syncthreads();
    }
    int running = partial[t] - s;
    for (int i = begin; i < end; i++) {
        offsets[i] = running;
        int c = counts[i];
        running += c;
        dinv[i] = rsqrtf((float)c + 1.0f);
    }
    if (t == 1023) offsets[n] = partial[1023];
}

__global__ void scatter_kernel(const int* __restrict__ ei, long long E,
                               int* __restrict__ cursor,
                               int* __restrict__ csr_src) {
    long long e = blockIdx.x * (long long)blockDim.x + threadIdx.x;
    if (e < E) {
        int s = ei[e];
        int d = ei[E + e];
        int pos = atomicAdd(&cursor[d], 1);
        csr_src[pos] = s;
    }
}

// ---------------------------------------------------------------------------
// Tensor-core GEMM (R13): out[n,M] = act(X)[n,K] @ W[K,M] (optionally *dinv),
// m16n8k8 tf32 / 3xTF32. ROWS=64/block; warp (wq,wh) owns 16 rows x M/2.
// X staged in smem (K+4 pad). W staged CK rows at a time, single buffer,
// row stride MP=M+8 -> conflict-free B-frag LDS.
template <int K, int M, bool BN, bool SCALE, int MAXB, int CK>
__global__ void __launch_bounds__(256, MAXB)
gemm_tc_kernel(const float* __restrict__ X,
               const float* __restrict__ W,
               float* __restrict__ out, int n,
               const float* __restrict__ stats,
               const float* __restrict__ g,
               const float* __restrict__ beta,
               const float* __restrict__ dinv) {
    constexpr int ROWS = 64;
    constexpr int KP   = K + 4;
    constexpr int MP   = M + 8;
    constexpr int NT   = M / 16;

    extern __shared__ float sh[];
    float* xs     = sh;                   // ROWS*KP
    float* whi    = xs + ROWS * KP;       // CK*MP
    float* wlo    = whi + CK * MP;        // CK*MP
    float* sscale = wlo + CK * MP;        // K
    float* sshift = sscale + K;           // K

    const int tid  = threadIdx.x;
    const int lane = tid & 31;
    const int wid  = tid >> 5;

    if (BN) {
        for (int f = tid; f < K; f += 256) {
            float inv_n = 1.0f / (float)n;
            float m = stats[f] * inv_n;
            float v = stats[128 + f] * inv_n - m * m;
            float sc = g[f] * rsqrtf(v + 1e-5f);
            sscale[f] = sc;
            sshift[f] = beta[f] - m * sc;
        }
        __syncthreads();
    }

    const int base = blockIdx.x * ROWS;
    constexpr int K4 = K / 4;
    for (int i = tid; i < ROWS * K4; i += 256) {
        int rr = i / K4, kk = i % K4;
        int row = base + rr;
        float4 v = make_float4(0.f, 0.f, 0.f, 0.f);
        if (row < n) {
            v = *(const float4*)(X + (long long)row * K + kk * 4);
            if (BN) {
                int f = kk * 4;
                v.x = fmaxf(fmaf(v.x, sscale[f + 0], sshift[f + 0]), 0.f);
                v.y = fmaxf(fmaf(v.y, sscale[f + 1], sshift[f + 1]), 0.f);
                v.z = fmaxf(fmaf(v.z, sscale[f + 2], sshift[f + 2]), 0.f);
                v.w = fmaxf(fmaf(v.w, sscale[f + 3], sshift[f + 3]), 0.f);
            }
        }
        *(float4*)&xs[rr * KP + kk * 4] = v;
    }

    const int fr = lane >> 2;
    const int fc = lane & 3;
    const int wq = wid & 3;
    const int wh = wid >> 2;
    const int wrow = wq * 16;
    const int ncol0 = wh * (M / 2);

    float acc[NT][4];
#pragma unroll
    for (int t = 0; t < NT; t++)
#pragma unroll
        for (int j = 0; j < 4; j++) acc[t][j] = 0.0f;

    const float* xw0 = xs + (wrow + fr) * KP;
    const float* xw1 = xs + (wrow + fr + 8) * KP;

    for (int ck = 0; ck < K / CK; ck++) {
        __syncthreads();
        constexpr int M4 = M / 4;
        for (int i = tid; i < CK * M4; i += 256) {
            int kk = i / M4, mm = i % M4;
            float4 w = __ldg((const float4*)(W + (ck * CK + kk) * M + mm * 4));
            float4 h, l;
            h.x = __uint_as_float(f2tf32(w.x)); l.x = __uint_as_float(f2tf32(w.x - h.x));
            h.y = __uint_as_float(f2tf32(w.y)); l.y = __uint_as_float(f2tf32(w.y - h.y));
            h.z = __uint_as_float(f2tf32(w.z)); l.z = __uint_as_float(f2tf32(w.z - h.z));
            h.w = __uint_as_float(f2tf32(w.w)); l.w = __uint_as_float(f2tf32(w.w - h.w));
            *(float4*)&whi[kk * MP + mm * 4] = h;
            *(float4*)&wlo[kk * MP + mm * 4] = l;
        }
        __syncthreads();

#pragma unroll
        for (int kc = 0; kc < CK / 8; kc++) {
            const int kg = ck * CK + kc * 8 + fc;
            float af0 = xw0[kg];
            float af1 = xw1[kg];
            float af2 = xw0[kg + 4];
            float af3 = xw1[kg + 4];
            unsigned ah[4], al[4];
            ah[0] = f2tf32(af0); al[0] = f2tf32(af0 - __uint_as_float(ah[0]));
            ah[1] = f2tf32(af1); al[1] = f2tf32(af1 - __uint_as_float(ah[1]));
            ah[2] = f2tf32(af2); al[2] = f2tf32(af2 - __uint_as_float(ah[2]));
            ah[3] = f2tf32(af3); al[3] = f2tf32(af3 - __uint_as_float(ah[3]));

            const int kl0 = (kc * 8 + fc) * MP;
            const int kl1 = kl0 + 4 * MP;
#pragma unroll
            for (int t = 0; t < NT; t++) {
                const int cb = ncol0 + t * 8 + fr;
                unsigned bh0 = __float_as_uint(whi[kl0 + cb]);
                unsigned bh1 = __float_as_uint(whi[kl1 + cb]);
                unsigned bl0 = __float_as_uint(wlo[kl0 + cb]);
                unsigned bl1 = __float_as_uint(wlo[kl1 + cb]);
                mma_tf32(acc[t], ah, bh0, bh1);
                mma_tf32(acc[t], al, bh0, bh1);
                mma_tf32(acc[t], ah, bl0, bl1);
            }
        }
    }

    const int row0 = base + wrow + fr;
    const int row1 = row0 + 8;
    float s0 = 1.0f, s1 = 1.0f;
    if (SCALE) {
        if (row0 < n) s0 = dinv[row0];
        if (row1 < n) s1 = dinv[row1];
    }
#pragma unroll
    for (int t = 0; t < NT; t++) {
        const int col = ncol0 + t * 8 + 2 * fc;
        if (row0 < n)
            *(float2*)&out[(long long)row0 * M + col] =
                make_float2(acc[t][0] * s0, acc[t][1] * s0);
        if (row1 < n)
            *(float2*)&out[(long long)row1 * M + col] =
                make_float2(acc[t][2] * s1, acc[t][3] * s1);
    }
}

// Small GEMM for M=2 (layer 3), BN+ReLU fused on load, output scaled by dinv.
template <int K>
__global__ void gemm2_bn_kernel(const float* __restrict__ X,
                                const float* __restrict__ W,
                                float* __restrict__ out, int n,
                                const float* __restrict__ stats,
                                const float* __restrict__ g,
                                const float* __restrict__ beta,
                                const float* __restrict__ dinv) {
    __shared__ float Ws[K * 2];
    __shared__ float sscale[K];
    __shared__ float sshift[K];
    __shared__ float xs[128 * K];
    const int tid = threadIdx.x;

    if (tid < K) {
        float inv_n = 1.0f / (float)n;
        float m = stats[tid] * inv_n;
        float v = stats[128 + tid] * inv_n - m * m;
        float sc = g[tid] * rsqrtf(v + 1e-5f);
        sscale[tid] = sc;
        sshift[tid] = beta[tid] - m * sc;
    }
    for (int i = tid; i < K * 2; i += 256) Ws[i] = W[i];
    __syncthreads();

    const int base = blockIdx.x * 128;
    constexpr int K4 = K / 4;
    for (int i = tid; i < 128 * K4; i += 256) {
        int rr = i / K4, kk = i % K4;
        int row = base + rr;
        float4 v = make_float4(0.f, 0.f, 0.f, 0.f);
        if (row < n) {
            v = *(const float4*)(X + (long long)row * K + kk * 4);
            int f = kk * 4;
            v.x = fmaxf(fmaf(v.x, sscale[f + 0], sshift[f + 0]), 0.f);
            v.y = fmaxf(fmaf(v.y, sscale[f + 1], sshift[f + 1]), 0.f);
            v.z = fmaxf(fmaf(v.z, sscale[f + 2], sshift[f + 2]), 0.f);
            v.w = fmaxf(fmaf(v.w, sscale[f + 3], sshift[f + 3]), 0.f);
        }
        *(float4*)&xs[rr * K + kk * 4] = v;
    }
    __syncthreads();

    const int col = tid % 2;
    const int r   = tid / 2;
    int row = base + r;
    if (row < n) {
        float acc = 0.0f;
        const float* xrow = xs + r * K;
#pragma unroll
        for (int k = 0; k < K; k++) acc = fmaf(xrow[k], Ws[k * 2 + col], acc);
        out[(long long)row * 2 + col] = acc * dinv[row];
    }
}

// ---------------------------------------------------------------------------
// CSR pull-aggregation, F=128, UNSCALED input h (layer 1).
__global__ void __launch_bounds__(256)
csr_agg128_kernel(const int* __restrict__ csr_src,
                  const int* __restrict__ offsets,
                  const float* __restrict__ h,
                  const float* __restrict__ dinv,
                  const float* __restrict__ b,
                  float* __restrict__ out, int n,
                  float* __restrict__ stats) {
    __shared__ float ssum[128];
    __shared__ float ssq[128];
    const int tid  = threadIdx.x;
    const int lane = tid & 31;
    const int wid  = tid >> 5;
    if (tid < 128) { ssum[tid] = 0.f; ssq[tid] = 0.f; }
    __syncthreads();

    const float4* h4 = (const float4*)h;
    float4* out4 = (float4*)out;
    float4 bv = ((const float4*)b)[lane];

    float4 lsum = make_float4(0.f, 0.f, 0.f, 0.f);
    float4 lsq  = make_float4(0.f, 0.f, 0.f, 0.f);

    for (int node = blockIdx.x * 8 + wid; node < n; node += gridDim.x * 8) {
        const int e0 = offsets[node];
        const int e1 = offsets[node + 1];
        const float dn = dinv[node];
        float4 acc = make_float4(0.f, 0.f, 0.f, 0.f);

        int j = e0;
        for (; j + 4 <= e1; j += 4) {
            int sa = csr_src[j],     sb = csr_src[j + 1];
            int sc = csr_src[j + 2], sd = csr_src[j + 3];
            float na = dinv[sa] * dn, nb = dinv[sb] * dn;
            float nc = dinv[sc] * dn, nd = dinv[sd] * dn;
            float4 va = h4[(long long)sa * 32 + lane];
            float4 vb = h4[(long long)sb * 32 + lane];
            float4 vc = h4[(long long)sc * 32 + lane];
            float4 vd = h4[(long long)sd * 32 + lane];
            acc.x += va.x * na + vb.x * nb + vc.x * nc + vd.x * nd;
            acc.y += va.y * na + vb.y * nb + vc.y * nc + vd.y * nd;
            acc.z += va.z * na + vb.z * nb + vc.z * nc + vd.z * nd;
            acc.w += va.w * na + vb.w * nb + vc.w * nc + vd.w * nd;
        }
        for (; j < e1; j++) {
            int s = csr_src[j];
            float nm = dinv[s] * dn;
            float4 v = h4[(long long)s * 32 + lane];
            acc.x += v.x * nm; acc.y += v.y * nm;
            acc.z += v.z * nm; acc.w += v.w * nm;
        }
        float4 hv = h4[(long long)node * 32 + lane];
        float d2 = dn * dn;
        acc.x = fmaf(hv.x, d2, acc.x) + bv.x;
        acc.y = fmaf(hv.y, d2, acc.y) + bv.y;
        acc.z = fmaf(hv.z, d2, acc.z) + bv.z;
        acc.w = fmaf(hv.w, d2, acc.w) + bv.w;
        out4[(long long)node * 32 + lane] = acc;

        lsum.x += acc.x; lsum.y += acc.y; lsum.z += acc.z; lsum.w += acc.w;
        lsq.x = fmaf(acc.x, acc.x, lsq.x); lsq.y = fmaf(acc.y, acc.y, lsq.y);
        lsq.z = fmaf(acc.z, acc.z, lsq.z); lsq.w = fmaf(acc.w, acc.w, lsq.w);
    }

    atomicAdd(&ssum[lane * 4 + 0], lsum.x);
    atomicAdd(&ssum[lane * 4 + 1], lsum.y);
    atomicAdd(&ssum[lane * 4 + 2], lsum.z);
    atomicAdd(&ssum[lane * 4 + 3], lsum.w);
    atomicAdd(&ssq[lane * 4 + 0], lsq.x);
    atomicAdd(&ssq[lane * 4 + 1], lsq.y);
    atomicAdd(&ssq[lane * 4 + 2], lsq.z);
    atomicAdd(&ssq[lane * 4 + 3], lsq.w);
    __syncthreads();
    if (tid < 128) {
        atomicAdd(&stats[tid], ssum[tid]);
        atomicAdd(&stats[128 + tid], ssq[tid]);
    }
}

// F=64, PRE-SCALED input h' = h*dinv[src]; inner loop = pure adds.
__global__ void __launch_bounds__(256)
csr_agg64_kernel(const int* __restrict__ csr_src,
                 const int* __restrict__ offsets,
                 const float* __restrict__ h,
                 const float* __restrict__ dinv,
                 const float* __restrict__ b,
                 float* __restrict__ out, int n,
                 float* __restrict__ stats) {
    __shared__ float ssum[64];
    __shared__ float ssq[64];
    const int tid  = threadIdx.x;
    const int lane = tid & 31;
    const int wid  = tid >> 5;
    if (tid < 64) { ssum[tid] = 0.f; ssq[tid] = 0.f; }
    __syncthreads();

    const float2* h2 = (const float2*)h;
    float2* out2 = (float2*)out;
    float2 bv = ((const float2*)b)[lane];

    float2 lsum = make_float2(0.f, 0.f);
    float2 lsq  = make_float2(0.f, 0.f);

    for (int node = blockIdx.x * 8 + wid; node < n; node += gridDim.x * 8) {
        const int e0 = offsets[node];
        const int e1 = offsets[node + 1];
        const float dn = dinv[node];
        float2 acc = make_float2(0.f, 0.f);

        int j = e0;
        for (; j + 4 <= e1; j += 4) {
            int sa = csr_src[j],     sb = csr_src[j + 1];
            int sc = csr_src[j + 2], sd = csr_src[j + 3];
            float2 va = h2[(long long)sa * 32 + lane];
            float2 vb = h2[(long long)sb * 32 + lane];
            float2 vc = h2[(long long)sc * 32 + lane];
            float2 vd = h2[(long long)sd * 32 + lane];
            acc.x += va.x + vb.x + vc.x + vd.x;
            acc.y += va.y + vb.y + vc.y + vd.y;
        }
        for (; j < e1; j++) {
            int s = csr_src[j];
            float2 v = h2[(long long)s * 32 + lane];
            acc.x += v.x; acc.y += v.y;
        }
        float2 hv = h2[(long long)node * 32 + lane];
        float2 o;
        o.x = fmaf(dn, acc.x + hv.x, bv.x);
        o.y = fmaf(dn, acc.y + hv.y, bv.y);
        out2[(long long)node * 32 + lane] = o;

        lsum.x += o.x; lsum.y += o.y;
        lsq.x = fmaf(o.x, o.x, lsq.x);
        lsq.y = fmaf(o.y, o.y, lsq.y);
    }

    atomicAdd(&ssum[lane * 2 + 0], lsum.x);
    atomicAdd(&ssum[lane * 2 + 1], lsum.y);
    atomicAdd(&ssq[lane * 2 + 0], lsq.x);
    atomicAdd(&ssq[lane * 2 + 1], lsq.y);
    __syncthreads();
    if (tid < 64) {
        atomicAdd(&stats[tid], ssum[tid]);
        atomicAdd(&stats[128 + tid], ssq[tid]);
    }
}

// F=2, PRE-SCALED h'; fuses bias + log_softmax, writes d_out.
__global__ void __launch_bounds__(256)
csr_agg2_lsm_kernel(const int* __restrict__ csr_src,
                    const int* __restrict__ offsets,
                    const float* __restrict__ h,
                    const float* __restrict__ dinv,
                    const float* __restrict__ b,
                    float* __restrict__ out, int n) {
    int node = blockIdx.x * blockDim.x + threadIdx.x;
    if (node >= n) return;
    const float2* h2 = (const float2*)h;
    const int e0 = offsets[node];
    const int e1 = offsets[node + 1];
    const float dn = dinv[node];
    float ax = 0.f, ay = 0.f;
    int j = e0;
    for (; j + 4 <= e1; j += 4) {
        int sa = csr_src[j],     sb = csr_src[j + 1];
        int sc = csr_src[j + 2], sd = csr_src[j + 3];
        float2 va = h2[sa], vb = h2[sb], vc = h2[sc], vd = h2[sd];
        ax += va.x + vb.x + vc.x + vd.x;
        ay += va.y + vb.y + vc.y + vd.y;
    }
    for (; j < e1; j++) {
        float2 v = h2[csr_src[j]];
        ax += v.x; ay += v.y;
    }
    float2 hv = h2[node];
    float a = fmaf(dn, ax + hv.x, b[0]);
    float c = fmaf(dn, ay + hv.y, b[1]);
    float m = fmaxf(a, c);
    float l = m + logf(expf(a - m) + expf(c - m));
    out[2 * node]     = a - l;
    out[2 * node + 1] = c - l;
}

// ---------------------------------------------------------------------------
static inline int blocks_for(long long total, int tpb) {
    return (int)((total + tpb - 1) / tpb);
}

template <int K, int M, bool BN, bool SCALE, int MAXB, int CK>
static void launch_gemm_tc(const float* X, const float* W, float* out, int n,
                           const float* stats, const float* g,
                           const float* beta, const float* dinv) {
    constexpr int ROWS = 64;
    constexpr int KP = K + 4;
    constexpr int MP = M + 8;
    size_t sh = (size_t)(ROWS * KP + 2 * CK * MP + 2 * K) * sizeof(float);
    cudaFuncSetAttribute(gemm_tc_kernel<K, M, BN, SCALE, MAXB, CK>,
                         cudaFuncAttributeMaxDynamicSharedMemorySize, (int)sh);
    int grid = (n + ROWS - 1) / ROWS;
    gemm_tc_kernel<K, M, BN, SCALE, MAXB, CK><<<grid, 256, sh>>>(
        X, W, out, n, stats, g, beta, dinv);
}

extern "C" void kernel_launch(void* const* d_in, const int* in_sizes, int n_in,
                              void* d_out, int out_size) {
    const float* x   = (const float*)d_in[0];
    const int*   ei  = (const int*)d_in[1];
    const float* W1 = (const float*)d_in[2];
    const float* b1 = (const float*)d_in[3];
    const float* g1 = (const float*)d_in[4];
    const float* be1= (const float*)d_in[5];
    const float* W2 = (const float*)d_in[6];
    const float* b2 = (const float*)d_in[7];
    const float* g2 = (const float*)d_in[8];
    const float* be2= (const float*)d_in[9];
    const float* W3 = (const float*)d_in[10];
    const float* b3 = (const float*)d_in[11];
    float* out = (float*)d_out;

    int       n = in_sizes[0] / 128;
    long long E = in_sizes[1] / 2;

    float *bufA, *bufB, *dinv, *stats;
    int *counts, *offsets, *cursor, *csr_src;
    cudaGetSymbolAddress((void**)&bufA,    g_bufA);
    cudaGetSymbolAddress((void**)&bufB,    g_bufB);
    cudaGetSymbolAddress((void**)&dinv,    g_dinv);
    cudaGetSymbolAddress((void**)&stats,   g_stats);
    cudaGetSymbolAddress((void**)&counts,  g_counts);
    cudaGetSymbolAddress((void**)&offsets, g_offsets);
    cudaGetSymbolAddress((void**)&cursor,  g_cursor);
    cudaGetSymbolAddress((void**)&csr_src, g_csr_src);
    float* statsA = stats;        // layer-1 BN stats
    float* statsB = stats + 256;  // layer-2 BN stats

    static cudaStream_t s_side = nullptr;
    static cudaEvent_t ev_fork = nullptr, ev_join = nullptr;
    if (s_side == nullptr) {
        cudaStreamCreateWithFlags(&s_side, cudaStreamNonBlocking);
        cudaEventCreateWithFlags(&ev_fork, cudaEventDisableTiming);
        cudaEventCreateWithFlags(&ev_join, cudaEventDisableTiming);
    }

    const int AGG_GRID = 1184;

    // ---- fork: CSR build + dinv + both stats zeroed on side stream ----------
    cudaEventRecord(ev_fork, 0);
    cudaStreamWaitEvent(s_side, ev_fork, 0);
    cudaMemsetAsync(counts, 0, (size_t)n * sizeof(int), s_side);
    hist_kernel<<<blocks_for(E, 256), 256, 0, s_side>>>(ei, E, counts);
    scan_kernel<<<1, 1024, 0, s_side>>>(counts, offsets, dinv, n);
    cudaMemcpyAsync(cursor, offsets, (size_t)n * sizeof(int),
                    cudaMemcpyDeviceToDevice, s_side);
    scatter_kernel<<<blocks_for(E, 256), 256, 0, s_side>>>(ei, E, cursor, csr_src);
    cudaMemsetAsync(stats, 0, 512 * sizeof(float), s_side);
    cudaEventRecord(ev_join, s_side);

    // ---- layer 1 TC-GEMM (single-buffer; concurrent with CSR build) ---------
    launch_gemm_tc<128, 128, false, false, 3, 16>(
        x, W1, bufA, n, nullptr, nullptr, nullptr, nullptr);

    // ---- join, aggregation + rest of chain ----------------------------------
    cudaStreamWaitEvent(0, ev_join, 0);
    csr_agg128_kernel<<<AGG_GRID, 256>>>(csr_src, offsets, bufA, dinv, b1,
                                         bufB, n, statsA);

    // ---- layer 2: BN1+ReLU fused TC-GEMM(128->64) * dinv --------------------
    launch_gemm_tc<128, 64, true, true, 4, 8>(
        bufB, W2, bufA, n, statsA, g1, be1, dinv);
    csr_agg64_kernel<<<AGG_GRID, 256>>>(csr_src, offsets, bufA, dinv, b2,
                                        bufB, n, statsB);

    // ---- layer 3: BN2+ReLU fused GEMM(64->2) * dinv + agg + log_softmax -----
    gemm2_bn_kernel<64><<<blocks_for(n, 128), 256>>>(bufB, W3, bufA, n,
                                                     statsB, g2, be2, dinv);
    csr_agg2_lsm_kernel<<<blocks_for(n, 256), 256>>>(csr_src, offsets, bufA,
                                                     dinv, b3, out, n);
}

// round 17
// speedup vs baseline: 1.2202x; 1.0256x over previous
#include <cuda_runtime.h>
#include <cuda_bf16.h>
#include <math.h>

// ---------------------------------------------------------------------------
// FraudGNN: 3-layer GCN, N=50000 nodes, E=800000 edges (int32 edge_index).
// R17 = R16 (proven 258us config) + 8-way unrolled gathers in the CSR
// aggregation kernels (MLP 4 -> 8) to cover L2 latency. Nothing else changed.
// ---------------------------------------------------------------------------

#define NMAX 50000
#define EMAX 800000

__device__ float g_bufA[NMAX * 128];
__device__ float g_bufB[NMAX * 128];
__device__ float g_dinv[NMAX];
__device__ float g_stats[512];        // [0..255] layer1, [256..511] layer2
__device__ int   g_counts[NMAX];
__device__ int   g_offsets[NMAX + 1];
__device__ int   g_cursor[NMAX];
__device__ int   g_csr_src[EMAX];

// ---------------------------------------------------------------------------
__device__ __forceinline__ unsigned f2tf32(float f) {
    unsigned u;
    asm("cvt.rna.tf32.f32 %0, %1;" : "=r"(u) : "f"(f));
    return u;
}

__device__ __forceinline__ void mma_tf32(float* c, const unsigned* a,
                                         unsigned b0, unsigned b1) {
    asm volatile(
        "mma.sync.aligned.m16n8k8.row.col.f32.tf32.tf32.f32 "
        "{%0,%1,%2,%3},{%4,%5,%6,%7},{%8,%9},{%0,%1,%2,%3};"
        : "+f"(c[0]), "+f"(c[1]), "+f"(c[2]), "+f"(c[3])
        : "r"(a[0]), "r"(a[1]), "r"(a[2]), "r"(a[3]), "r"(b0), "r"(b1));
}

// ---------------------------------------------------------------------------
__global__ void hist_kernel(const int* __restrict__ ei, long long E,
                            int* __restrict__ counts) {
    long long e = blockIdx.x * (long long)blockDim.x + threadIdx.x;
    if (e < E) atomicAdd(&counts[ei[E + e]], 1);
}

__global__ void scan_kernel(const int* __restrict__ counts,
                            int* __restrict__ offsets,
                            float* __restrict__ dinv, int n) {
    __shared__ int partial[1024];
    const int t = threadIdx.x;
    const int chunk = (n + 1023) / 1024;
    const int begin = t * chunk;
    const int end = min(begin + chunk, n);
    int s = 0;
#pragma unroll 4
    for (int i = begin; i < end; i++) s += counts[i];
    partial[t] = s;
    __syncthreads();
    for (int off = 1; off < 1024; off <<= 1) {
        int x = (t >= off) ? partial[t - off] : 0;
        __syncthreads();
        partial[t] += x;
        __syncthreads();
    }
    int running = partial[t] - s;
    for (int i = begin; i < end; i++) {
        offsets[i] = running;
        int c = counts[i];
        running += c;
        dinv[i] = rsqrtf((float)c + 1.0f);
    }
    if (t == 1023) offsets[n] = partial[1023];
}

__global__ void scatter_kernel(const int* __restrict__ ei, long long E,
                               int* __restrict__ cursor,
                               int* __restrict__ csr_src) {
    long long e = blockIdx.x * (long long)blockDim.x + threadIdx.x;
    if (e < E) {
        int s = ei[e];
        int d = ei[E + e];
        int pos = atomicAdd(&cursor[d], 1);
        csr_src[pos] = s;
    }
}

// ---------------------------------------------------------------------------
// Tensor-core GEMM (R13/R16): out[n,M] = act(X)[n,K] @ W[K,M] (opt *dinv),
// m16n8k8 tf32 / 3xTF32. ROWS=64/block; warp (wq,wh) owns 16 rows x M/2.
// X staged in smem (K+4 pad). W staged CK rows at a time, single buffer,
// row stride MP=M+8 -> conflict-free B-frag LDS.
template <int K, int M, bool BN, bool SCALE, int MAXB, int CK>
__global__ void __launch_bounds__(256, MAXB)
gemm_tc_kernel(const float* __restrict__ X,
               const float* __restrict__ W,
               float* __restrict__ out, int n,
               const float* __restrict__ stats,
               const float* __restrict__ g,
               const float* __restrict__ beta,
               const float* __restrict__ dinv) {
    constexpr int ROWS = 64;
    constexpr int KP   = K + 4;
    constexpr int MP   = M + 8;
    constexpr int NT   = M / 16;

    extern __shared__ float sh[];
    float* xs     = sh;                   // ROWS*KP
    float* whi    = xs + ROWS * KP;       // CK*MP
    float* wlo    = whi + CK * MP;        // CK*MP
    float* sscale = wlo + CK * MP;        // K
    float* sshift = sscale + K;           // K

    const int tid  = threadIdx.x;
    const int lane = tid & 31;
    const int wid  = tid >> 5;

    if (BN) {
        for (int f = tid; f < K; f += 256) {
            float inv_n = 1.0f / (float)n;
            float m = stats[f] * inv_n;
            float v = stats[128 + f] * inv_n - m * m;
            float sc = g[f] * rsqrtf(v + 1e-5f);
            sscale[f] = sc;
            sshift[f] = beta[f] - m * sc;
        }
        __syncthreads();
    }

    const int base = blockIdx.x * ROWS;
    constexpr int K4 = K / 4;
    for (int i = tid; i < ROWS * K4; i += 256) {
        int rr = i / K4, kk = i % K4;
        int row = base + rr;
        float4 v = make_float4(0.f, 0.f, 0.f, 0.f);
        if (row < n) {
            v = *(const float4*)(X + (long long)row * K + kk * 4);
            if (BN) {
                int f = kk * 4;
                v.x = fmaxf(fmaf(v.x, sscale[f + 0], sshift[f + 0]), 0.f);
                v.y = fmaxf(fmaf(v.y, sscale[f + 1], sshift[f + 1]), 0.f);
                v.z = fmaxf(fmaf(v.z, sscale[f + 2], sshift[f + 2]), 0.f);
                v.w = fmaxf(fmaf(v.w, sscale[f + 3], sshift[f + 3]), 0.f);
            }
        }
        *(float4*)&xs[rr * KP + kk * 4] = v;
    }

    const int fr = lane >> 2;
    const int fc = lane & 3;
    const int wq = wid & 3;
    const int wh = wid >> 2;
    const int wrow = wq * 16;
    const int ncol0 = wh * (M / 2);

    float acc[NT][4];
#pragma unroll
    for (int t = 0; t < NT; t++)
#pragma unroll
        for (int j = 0; j < 4; j++) acc[t][j] = 0.0f;

    const float* xw0 = xs + (wrow + fr) * KP;
    const float* xw1 = xs + (wrow + fr + 8) * KP;

    for (int ck = 0; ck < K / CK; ck++) {
        __syncthreads();
        constexpr int M4 = M / 4;
        for (int i = tid; i < CK * M4; i += 256) {
            int kk = i / M4, mm = i % M4;
            float4 w = __ldg((const float4*)(W + (ck * CK + kk) * M + mm * 4));
            float4 h, l;
            h.x = __uint_as_float(f2tf32(w.x)); l.x = __uint_as_float(f2tf32(w.x - h.x));
            h.y = __uint_as_float(f2tf32(w.y)); l.y = __uint_as_float(f2tf32(w.y - h.y));
            h.z = __uint_as_float(f2tf32(w.z)); l.z = __uint_as_float(f2tf32(w.z - h.z));
            h.w = __uint_as_float(f2tf32(w.w)); l.w = __uint_as_float(f2tf32(w.w - h.w));
            *(float4*)&whi[kk * MP + mm * 4] = h;
            *(float4*)&wlo[kk * MP + mm * 4] = l;
        }
        __syncthreads();

#pragma unroll
        for (int kc = 0; kc < CK / 8; kc++) {
            const int kg = ck * CK + kc * 8 + fc;
            float af0 = xw0[kg];
            float af1 = xw1[kg];
            float af2 = xw0[kg + 4];
            float af3 = xw1[kg + 4];
            unsigned ah[4], al[4];
            ah[0] = f2tf32(af0); al[0] = f2tf32(af0 - __uint_as_float(ah[0]));
            ah[1] = f2tf32(af1); al[1] = f2tf32(af1 - __uint_as_float(ah[1]));
            ah[2] = f2tf32(af2); al[2] = f2tf32(af2 - __uint_as_float(ah[2]));
            ah[3] = f2tf32(af3); al[3] = f2tf32(af3 - __uint_as_float(ah[3]));

            const int kl0 = (kc * 8 + fc) * MP;
            const int kl1 = kl0 + 4 * MP;
#pragma unroll
            for (int t = 0; t < NT; t++) {
                const int cb = ncol0 + t * 8 + fr;
                unsigned bh0 = __float_as_uint(whi[kl0 + cb]);
                unsigned bh1 = __float_as_uint(whi[kl1 + cb]);
                unsigned bl0 = __float_as_uint(wlo[kl0 + cb]);
                unsigned bl1 = __float_as_uint(wlo[kl1 + cb]);
                mma_tf32(acc[t], ah, bh0, bh1);
                mma_tf32(acc[t], al, bh0, bh1);
                mma_tf32(acc[t], ah, bl0, bl1);
            }
        }
    }

    const int row0 = base + wrow + fr;
    const int row1 = row0 + 8;
    float s0 = 1.0f, s1 = 1.0f;
    if (SCALE) {
        if (row0 < n) s0 = dinv[row0];
        if (row1 < n) s1 = dinv[row1];
    }
#pragma unroll
    for (int t = 0; t < NT; t++) {
        const int col = ncol0 + t * 8 + 2 * fc;
        if (row0 < n)
            *(float2*)&out[(long long)row0 * M + col] =
                make_float2(acc[t][0] * s0, acc[t][1] * s0);
        if (row1 < n)
            *(float2*)&out[(long long)row1 * M + col] =
                make_float2(acc[t][2] * s1, acc[t][3] * s1);
    }
}

// Small GEMM for M=2 (layer 3), BN+ReLU fused on load, output scaled by dinv.
template <int K>
__global__ void gemm2_bn_kernel(const float* __restrict__ X,
                                const float* __restrict__ W,
                                float* __restrict__ out, int n,
                                const float* __restrict__ stats,
                                const float* __restrict__ g,
                                const float* __restrict__ beta,
                                const float* __restrict__ dinv) {
    __shared__ float Ws[K * 2];
    __shared__ float sscale[K];
    __shared__ float sshift[K];
    __shared__ float xs[128 * K];
    const int tid = threadIdx.x;

    if (tid < K) {
        float inv_n = 1.0f / (float)n;
        float m = stats[tid] * inv_n;
        float v = stats[128 + tid] * inv_n - m * m;
        float sc = g[tid] * rsqrtf(v + 1e-5f);
        sscale[tid] = sc;
        sshift[tid] = beta[tid] - m * sc;
    }
    for (int i = tid; i < K * 2; i += 256) Ws[i] = W[i];
    __syncthreads();

    const int base = blockIdx.x * 128;
    constexpr int K4 = K / 4;
    for (int i = tid; i < 128 * K4; i += 256) {
        int rr = i / K4, kk = i % K4;
        int row = base + rr;
        float4 v = make_float4(0.f, 0.f, 0.f, 0.f);
        if (row < n) {
            v = *(const float4*)(X + (long long)row * K + kk * 4);
            int f = kk * 4;
            v.x = fmaxf(fmaf(v.x, sscale[f + 0], sshift[f + 0]), 0.f);
            v.y = fmaxf(fmaf(v.y, sscale[f + 1], sshift[f + 1]), 0.f);
            v.z = fmaxf(fmaf(v.z, sscale[f + 2], sshift[f + 2]), 0.f);
            v.w = fmaxf(fmaf(v.w, sscale[f + 3], sshift[f + 3]), 0.f);
        }
        *(float4*)&xs[rr * K + kk * 4] = v;
    }
    __syncthreads();

    const int col = tid % 2;
    const int r   = tid / 2;
    int row = base + r;
    if (row < n) {
        float acc = 0.0f;
        const float* xrow = xs + r * K;
#pragma unroll
        for (int k = 0; k < K; k++) acc = fmaf(xrow[k], Ws[k * 2 + col], acc);
        out[(long long)row * 2 + col] = acc * dinv[row];
    }
}

// ---------------------------------------------------------------------------
// CSR pull-aggregation, F=128, UNSCALED input h (layer 1). 8-way unrolled
// gather (8 independent float4 loads in flight per warp).
// out = dn*(sum h[s]*dinv[s] + dn*h[node]) + b.
__global__ void __launch_bounds__(256)
csr_agg128_kernel(const int* __restrict__ csr_src,
                  const int* __restrict__ offsets,
                  const float* __restrict__ h,
                  const float* __restrict__ dinv,
                  const float* __restrict__ b,
                  float* __restrict__ out, int n,
                  float* __restrict__ stats) {
    __shared__ float ssum[128];
    __shared__ float ssq[128];
    const int tid  = threadIdx.x;
    const int lane = tid & 31;
    const int wid  = tid >> 5;
    if (tid < 128) { ssum[tid] = 0.f; ssq[tid] = 0.f; }
    __syncthreads();

    const float4* h4 = (const float4*)h;
    float4* out4 = (float4*)out;
    float4 bv = ((const float4*)b)[lane];

    float4 lsum = make_float4(0.f, 0.f, 0.f, 0.f);
    float4 lsq  = make_float4(0.f, 0.f, 0.f, 0.f);

    for (int node = blockIdx.x * 8 + wid; node < n; node += gridDim.x * 8) {
        const int e0 = offsets[node];
        const int e1 = offsets[node + 1];
        const float dn = dinv[node];
        float4 acc = make_float4(0.f, 0.f, 0.f, 0.f);

        int j = e0;
        for (; j + 8 <= e1; j += 8) {
            int s0 = csr_src[j],     s1 = csr_src[j + 1];
            int s2 = csr_src[j + 2], s3 = csr_src[j + 3];
            int s4 = csr_src[j + 4], s5 = csr_src[j + 5];
            int s6 = csr_src[j + 6], s7 = csr_src[j + 7];
            float n0 = dinv[s0], n1 = dinv[s1], n2 = dinv[s2], n3 = dinv[s3];
            float n4 = dinv[s4], n5 = dinv[s5], n6 = dinv[s6], n7 = dinv[s7];
            float4 v0 = h4[(long long)s0 * 32 + lane];
            float4 v1 = h4[(long long)s1 * 32 + lane];
            float4 v2 = h4[(long long)s2 * 32 + lane];
            float4 v3 = h4[(long long)s3 * 32 + lane];
            float4 v4 = h4[(long long)s4 * 32 + lane];
            float4 v5 = h4[(long long)s5 * 32 + lane];
            float4 v6 = h4[(long long)s6 * 32 + lane];
            float4 v7 = h4[(long long)s7 * 32 + lane];
            acc.x += v0.x * n0 + v1.x * n1 + v2.x * n2 + v3.x * n3
                   + v4.x * n4 + v5.x * n5 + v6.x * n6 + v7.x * n7;
            acc.y += v0.y * n0 + v1.y * n1 + v2.y * n2 + v3.y * n3
                   + v4.y * n4 + v5.y * n5 + v6.y * n6 + v7.y * n7;
            acc.z += v0.z * n0 + v1.z * n1 + v2.z * n2 + v3.z * n3
                   + v4.z * n4 + v5.z * n5 + v6.z * n6 + v7.z * n7;
            acc.w += v0.w * n0 + v1.w * n1 + v2.w * n2 + v3.w * n3
                   + v4.w * n4 + v5.w * n5 + v6.w * n6 + v7.w * n7;
        }
        for (; j < e1; j++) {
            int s = csr_src[j];
            float nm = dinv[s];
            float4 v = h4[(long long)s * 32 + lane];
            acc.x += v.x * nm; acc.y += v.y * nm;
            acc.z += v.z * nm; acc.w += v.w * nm;
        }
        float4 hv = h4[(long long)node * 32 + lane];
        float4 o;
        o.x = fmaf(dn, fmaf(hv.x, dn, acc.x), bv.x);
        o.y = fmaf(dn, fmaf(hv.y, dn, acc.y), bv.y);
        o.z = fmaf(dn, fmaf(hv.z, dn, acc.z), bv.z);
        o.w = fmaf(dn, fmaf(hv.w, dn, acc.w), bv.w);
        out4[(long long)node * 32 + lane] = o;

        lsum.x += o.x; lsum.y += o.y; lsum.z += o.z; lsum.w += o.w;
        lsq.x = fmaf(o.x, o.x, lsq.x); lsq.y = fmaf(o.y, o.y, lsq.y);
        lsq.z = fmaf(o.z, o.z, lsq.z); lsq.w = fmaf(o.w, o.w, lsq.w);
    }

    atomicAdd(&ssum[lane * 4 + 0], lsum.x);
    atomicAdd(&ssum[lane * 4 + 1], lsum.y);
    atomicAdd(&ssum[lane * 4 + 2], lsum.z);
    atomicAdd(&ssum[lane * 4 + 3], lsum.w);
    atomicAdd(&ssq[lane * 4 + 0], lsq.x);
    atomicAdd(&ssq[lane * 4 + 1], lsq.y);
    atomicAdd(&ssq[lane * 4 + 2], lsq.z);
    atomicAdd(&ssq[lane * 4 + 3], lsq.w);
    __syncthreads();
    if (tid < 128) {
        atomicAdd(&stats[tid], ssum[tid]);
        atomicAdd(&stats[128 + tid], ssq[tid]);
    }
}

// F=64, PRE-SCALED input h' = h*dinv[src]; pure adds, 8-way unroll.
__global__ void __launch_bounds__(256)
csr_agg64_kernel(const int* __restrict__ csr_src,
                 const int* __restrict__ offsets,
                 const float* __restrict__ h,
                 const float* __restrict__ dinv,
                 const float* __restrict__ b,
                 float* __restrict__ out, int n,
                 float* __restrict__ stats) {
    __shared__ float ssum[64];
    __shared__ float ssq[64];
    const int tid  = threadIdx.x;
    const int lane = tid & 31;
    const int wid  = tid >> 5;
    if (tid < 64) { ssum[tid] = 0.f; ssq[tid] = 0.f; }
    __syncthreads();

    const float2* h2 = (const float2*)h;
    float2* out2 = (float2*)out;
    float2 bv = ((const float2*)b)[lane];

    float2 lsum = make_float2(0.f, 0.f);
    float2 lsq  = make_float2(0.f, 0.f);

    for (int node = blockIdx.x * 8 + wid; node < n; node += gridDim.x * 8) {
        const int e0 = offsets[node];
        const int e1 = offsets[node + 1];
        const float dn = dinv[node];
        float2 acc = make_float2(0.f, 0.f);

        int j = e0;
        for (; j + 8 <= e1; j += 8) {
            int s0 = csr_src[j],     s1 = csr_src[j + 1];
            int s2 = csr_src[j + 2], s3 = csr_src[j + 3];
            int s4 = csr_src[j + 4], s5 = csr_src[j + 5];
            int s6 = csr_src[j + 6], s7 = csr_src[j + 7];
            float2 v0 = h2[(long long)s0 * 32 + lane];
            float2 v1 = h2[(long long)s1 * 32 + lane];
            float2 v2 = h2[(long long)s2 * 32 + lane];
            float2 v3 = h2[(long long)s3 * 32 + lane];
            float2 v4 = h2[(long long)s4 * 32 + lane];
            float2 v5 = h2[(long long)s5 * 32 + lane];
            float2 v6 = h2[(long long)s6 * 32 + lane];
            float2 v7 = h2[(long long)s7 * 32 + lane];
            acc.x += v0.x + v1.x + v2.x + v3.x + v4.x + v5.x + v6.x + v7.x;
            acc.y += v0.y + v1.y + v2.y + v3.y + v4.y + v5.y + v6.y + v7.y;
        }
        for (; j < e1; j++) {
            int s = csr_src[j];
            float2 v = h2[(long long)s * 32 + lane];
            acc.x += v.x; acc.y += v.y;
        }
        float2 hv = h2[(long long)node * 32 + lane];
        float2 o;
        o.x = fmaf(dn, acc.x + hv.x, bv.x);
        o.y = fmaf(dn, acc.y + hv.y, bv.y);
        out2[(long long)node * 32 + lane] = o;

        lsum.x += o.x; lsum.y += o.y;
        lsq.x = fmaf(o.x, o.x, lsq.x);
        lsq.y = fmaf(o.y, o.y, lsq.y);
    }

    atomicAdd(&ssum[lane * 2 + 0], lsum.x);
    atomicAdd(&ssum[lane * 2 + 1], lsum.y);
    atomicAdd(&ssq[lane * 2 + 0], lsq.x);
    atomicAdd(&ssq[lane * 2 + 1], lsq.y);
    __syncthreads();
    if (tid < 64) {
        atomicAdd(&stats[tid], ssum[tid]);
        atomicAdd(&stats[128 + tid], ssq[tid]);
    }
}

// F=2, PRE-SCALED h'; fuses bias + log_softmax, writes d_out. 8-way unroll.
__global__ void __launch_bounds__(256)
csr_agg2_lsm_kernel(const int* __restrict__ csr_src,
                    const int* __restrict__ offsets,
                    const float* __restrict__ h,
                    const float* __restrict__ dinv,
                    const float* __restrict__ b,
                    float* __restrict__ out, int n) {
    int node = blockIdx.x * blockDim.x + threadIdx.x;
    if (node >= n) return;
    const float2* h2 = (const float2*)h;
    const int e0 = offsets[node];
    const int e1 = offsets[node + 1];
    const float dn = dinv[node];
    float ax = 0.f, ay = 0.f;
    int j = e0;
    for (; j + 8 <= e1; j += 8) {
        int s0 = csr_src[j],     s1 = csr_src[j + 1];
        int s2 = csr_src[j + 2], s3 = csr_src[j + 3];
        int s4 = csr_src[j + 4], s5 = csr_src[j + 5];
        int s6 = csr_src[j + 6], s7 = csr_src[j + 7];
        float2 v0 = h2[s0], v1 = h2[s1], v2 = h2[s2], v3 = h2[s3];
        float2 v4 = h2[s4], v5 = h2[s5], v6 = h2[s6], v7 = h2[s7];
        ax += v0.x + v1.x + v2.x + v3.x + v4.x + v5.x + v6.x + v7.x;
        ay += v0.y + v1.y + v2.y + v3.y + v4.y + v5.y + v6.y + v7.y;
    }
    for (; j < e1; j++) {
        float2 v = h2[csr_src[j]];
        ax += v.x; ay += v.y;
    }
    float2 hv = h2[node];
    float a = fmaf(dn, ax + hv.x, b[0]);
    float c = fmaf(dn, ay + hv.y, b[1]);
    float m = fmaxf(a, c);
    float l = m + logf(expf(a - m) + expf(c - m));
    out[2 * node]     = a - l;
    out[2 * node + 1] = c - l;
}

// ---------------------------------------------------------------------------
static inline int blocks_for(long long total, int tpb) {
    return (int)((total + tpb - 1) / tpb);
}

template <int K, int M, bool BN, bool SCALE, int MAXB, int CK>
static void launch_gemm_tc(const float* X, const float* W, float* out, int n,
                           const float* stats, const float* g,
                           const float* beta, const float* dinv) {
    constexpr int ROWS = 64;
    constexpr int KP = K + 4;
    constexpr int MP = M + 8;
    size_t sh = (size_t)(ROWS * KP + 2 * CK * MP + 2 * K) * sizeof(float);
    cudaFuncSetAttribute(gemm_tc_kernel<K, M, BN, SCALE, MAXB, CK>,
                         cudaFuncAttributeMaxDynamicSharedMemorySize, (int)sh);
    int grid = (n + ROWS - 1) / ROWS;
    gemm_tc_kernel<K, M, BN, SCALE, MAXB, CK><<<grid, 256, sh>>>(
        X, W, out, n, stats, g, beta, dinv);
}

extern "C" void kernel_launch(void* const* d_in, const int* in_sizes, int n_in,
                              void* d_out, int out_size) {
    const float* x   = (const float*)d_in[0];
    const int*   ei  = (const int*)d_in[1];
    const float* W1 = (const float*)d_in[2];
    const float* b1 = (const float*)d_in[3];
    const float* g1 = (const float*)d_in[4];
    const float* be1= (const float*)d_in[5];
    const float* W2 = (const float*)d_in[6];
    const float* b2 = (const float*)d_in[7];
    const float* g2 = (const float*)d_in[8];
    const float* be2= (const float*)d_in[9];
    const float* W3 = (const float*)d_in[10];
    const float* b3 = (const float*)d_in[11];
    float* out = (float*)d_out;

    int       n = in_sizes[0] / 128;
    long long E = in_sizes[1] / 2;

    float *bufA, *bufB, *dinv, *stats;
    int *counts, *offsets, *cursor, *csr_src;
    cudaGetSymbolAddress((void**)&bufA,    g_bufA);
    cudaGetSymbolAddress((void**)&bufB,    g_bufB);
    cudaGetSymbolAddress((void**)&dinv,    g_dinv);
    cudaGetSymbolAddress((void**)&stats,   g_stats);
    cudaGetSymbolAddress((void**)&counts,  g_counts);
    cudaGetSymbolAddress((void**)&offsets, g_offsets);
    cudaGetSymbolAddress((void**)&cursor,  g_cursor);
    cudaGetSymbolAddress((void**)&csr_src, g_csr_src);
    float* statsA = stats;        // layer-1 BN stats
    float* statsB = stats + 256;  // layer-2 BN stats

    static cudaStream_t s_side = nullptr;
    static cudaEvent_t ev_fork = nullptr, ev_join = nullptr;
    if (s_side == nullptr) {
        cudaStreamCreateWithFlags(&s_side, cudaStreamNonBlocking);
        cudaEventCreateWithFlags(&ev_fork, cudaEventDisableTiming);
        cudaEventCreateWithFlags(&ev_join, cudaEventDisableTiming);
    }

    const int AGG_GRID = 1184;

    // ---- fork: CSR build + dinv + both stats zeroed on side stream ----------
    cudaEventRecord(ev_fork, 0);
    cudaStreamWaitEvent(s_side, ev_fork, 0);
    cudaMemsetAsync(counts, 0, (size_t)n * sizeof(int), s_side);
    hist_kernel<<<blocks_for(E, 256), 256, 0, s_side>>>(ei, E, counts);
    scan_kernel<<<1, 1024, 0, s_side>>>(counts, offsets, dinv, n);
    cudaMemcpyAsync(cursor, offsets, (size_t)n * sizeof(int),
                    cudaMemcpyDeviceToDevice, s_side);
    scatter_kernel<<<blocks_for(E, 256), 256, 0, s_side>>>(ei, E, cursor, csr_src);
    cudaMemsetAsync(stats, 0, 512 * sizeof(float), s_side);
    cudaEventRecord(ev_join, s_side);

    // ---- layer 1 TC-GEMM (single-buffer; concurrent with CSR build) ---------
    launch_gemm_tc<128, 128, false, false, 3, 16>(
        x, W1, bufA, n, nullptr, nullptr, nullptr, nullptr);

    // ---- join, aggregation + rest of chain ----------------------------------
    cudaStreamWaitEvent(0, ev_join, 0);
    csr_agg128_kernel<<<AGG_GRID, 256>>>(csr_src, offsets, bufA, dinv, b1,
                                         bufB, n, statsA);

    // ---- layer 2: BN1+ReLU fused TC-GEMM(128->64) * dinv --------------------
    launch_gemm_tc<128, 64, true, true, 4, 8>(
        bufB, W2, bufA, n, statsA, g1, be1, dinv);
    csr_agg64_kernel<<<AGG_GRID, 256>>>(csr_src, offsets, bufA, dinv, b2,
                                        bufB, n, statsB);

    // ---- layer 3: BN2+ReLU fused GEMM(64->2) * dinv + agg + log_softmax -----
    gemm2_bn_kernel<64><<<blocks_for(n, 128), 256>>>(bufB, W3, bufA, n,
                                                     statsB, g2, be2, dinv);
    csr_agg2_lsm_kernel<<<blocks_for(n, 256), 256>>>(csr_src, offsets, bufA,
                                                     dinv, b3, out, n);
}